// round 9
// baseline (speedup 1.0000x reference)
#include <cuda_runtime.h>
#include <math.h>
#include <stdint.h>

#define NB      23
#define NBIN    24
#define CELLS   (NBIN*NBIN)     // 576
#define BATCH   4
#define NVOX    884736
#define NK      17
#define NKEY    289             // 17x17 anchor keys
#define NBLKS   216             // sort-phase blocks/batch  (216*4096 = NVOX)
#define VPBS    4096
#define NBLKD   108             // accum-phase blocks/batch (108*8192 = NVOX)
#define VPBD    8192
#define CPT     32              // contiguous elements per thread in accum
#define K2EXP   (-1396.5287995805166f)   // -968 * log2(e)  (R1-proven recipe)

__device__ float2 g_sorted[(size_t)BATCH * NVOX];                 // 28.3 MB
__device__ int    g_hist[(size_t)BATCH * NBLKS * NKEY];
__device__ int    g_off [(size_t)BATCH * NBLKS * NKEY];
__device__ double g_bpart[(size_t)BATCH * NBLKD * CELLS];
__device__ double g_mi[BATCH];

// correctly-rounded bin centers i/22 (matches reference linspace to <=1 ulp)
#define C_(i) ((float)((double)(i) / 22.0))
__constant__ float BINC[NB] = {
    C_(0),C_(1),C_(2),C_(3),C_(4),C_(5),C_(6),C_(7),C_(8),C_(9),C_(10),
    C_(11),C_(12),C_(13),C_(14),C_(15),C_(16),C_(17),C_(18),C_(19),C_(20),
    C_(21),C_(22)
};

__device__ __forceinline__ int key_of(float x, float y, int& ax, int& ay) {
    float zx = 22.0f * fminf(fmaxf(x, 0.0f), 1.0f);
    float zy = 22.0f * fminf(fmaxf(y, 0.0f), 1.0f);
    ax = min(max(__float2int_rn(zx) - 3, 0), 16);
    ay = min(max(__float2int_rn(zy) - 3, 0), 16);
    return ax * NK + ay;
}

// ---- phase 1: per-block key histogram ----
__global__ __launch_bounds__(256)
void mi_hist(const float* __restrict__ pred, const float* __restrict__ target)
{
    __shared__ int h[NKEY];
    const int tid = threadIdx.x, b = blockIdx.y, blk = blockIdx.x;
    for (int k = tid; k < NKEY; k += 256) h[k] = 0;
    __syncthreads();
    const size_t base = (size_t)b * NVOX + (size_t)blk * VPBS;
    for (int s = 0; s < VPBS / 256; ++s) {
        const size_t i = base + s * 256 + tid;
        int ax, ay;
        atomicAdd(&h[key_of(pred[i], target[i], ax, ay)], 1);
    }
    __syncthreads();
    for (int k = tid; k < NKEY; k += 256)
        g_hist[((size_t)b * NBLKS + blk) * NKEY + k] = h[k];
}

// ---- phase 2: exclusive offsets per (block, key), deterministic ----
__global__ __launch_bounds__(512)
void mi_scan()
{
    __shared__ int tot[512];
    const int b = blockIdx.x, tid = threadIdx.x;
    int t = 0;
    if (tid < NKEY)
        for (int blk = 0; blk < NBLKS; ++blk)
            t += g_hist[((size_t)b * NBLKS + blk) * NKEY + tid];
    tot[tid] = t;
    __syncthreads();
    for (int o = 1; o < 512; o <<= 1) {
        int v = (tid >= o) ? tot[tid - o] : 0;
        __syncthreads();
        tot[tid] += v;
        __syncthreads();
    }
    if (tid < NKEY) {
        int run = (tid == 0) ? 0 : tot[tid - 1];
        for (int blk = 0; blk < NBLKS; ++blk) {
            const size_t idx = ((size_t)b * NBLKS + blk) * NKEY + tid;
            g_off[idx] = run;
            run += g_hist[idx];
        }
    }
}

// ---- phase 3: place voxel pairs into key-sorted array ----
__global__ __launch_bounds__(256)
void mi_place(const float* __restrict__ pred, const float* __restrict__ target)
{
    __shared__ int off[NKEY];
    const int tid = threadIdx.x, b = blockIdx.y, blk = blockIdx.x;
    for (int k = tid; k < NKEY; k += 256)
        off[k] = g_off[((size_t)b * NBLKS + blk) * NKEY + k];
    __syncthreads();
    const size_t base = (size_t)b * NVOX + (size_t)blk * VPBS;
    float2* __restrict__ dst = g_sorted + (size_t)b * NVOX;
    for (int s = 0; s < VPBS / 256; ++s) {
        const size_t i = base + s * 256 + tid;
        const float x = pred[i], y = target[i];
        int ax, ay;
        const int p = atomicAdd(&off[key_of(x, y, ax, ay)], 1);
        dst[p] = make_float2(x, y);
    }
}

// ---- phase 4: sparse 7x7 window accumulation, contiguous chunks ----
__global__ __launch_bounds__(256)
void mi_accum()
{
    __shared__ double sgrid[CELLS];
    const int tid = threadIdx.x, b = blockIdx.y, blk = blockIdx.x;
    for (int c = tid; c < CELLS; c += 256) sgrid[c] = 0.0;
    __syncthreads();

    // thread owns a CONTIGUOUS run of CPT sorted elements (few key changes)
    const float2* __restrict__ src =
        g_sorted + (size_t)b * NVOX + (size_t)blk * VPBD + (size_t)tid * CPT;

    float acc[49];
    #pragma unroll
    for (int c = 0; c < 49; ++c) acc[c] = 0.0f;
    int cur = -1;   // packed anchor: ax*32+ay

    for (int s = 0; s < CPT; ++s) {
        const float2 v = src[s];
        const float x = fminf(fmaxf(v.x, 0.0f), 1.0f);
        const float y = fminf(fmaxf(v.y, 0.0f), 1.0f);
        int ax, ay;
        (void)key_of(x, y, ax, ay);
        const int pk = ax * 32 + ay;

        if (pk != cur) {                       // flush previous window
            if (cur >= 0) {
                const int fa = cur >> 5, fb = cur & 31;
                #pragma unroll
                for (int i = 0; i < 7; ++i)
                    #pragma unroll
                    for (int j = 0; j < 7; ++j)
                        atomicAdd(&sgrid[(fa + i) * NBIN + fb + j],
                                  (double)acc[i * 7 + j]);
                #pragma unroll
                for (int c = 0; c < 49; ++c) acc[c] = 0.0f;
            }
            cur = pk;
        }

        // R1-proven weight arithmetic: exp2f (accurate), x-space distances
        float wa[7], wb[7], Sa = 0.0f, Sb = 0.0f;
        #pragma unroll
        for (int t = 0; t < 7; ++t) {
            const float d = x - BINC[ax + t];
            wa[t] = exp2f(K2EXP * d * d);
            Sa += wa[t];
        }
        #pragma unroll
        for (int t = 0; t < 7; ++t) {
            const float d = y - BINC[ay + t];
            wb[t] = exp2f(K2EXP * d * d);
            Sb += wb[t];
        }
        const float rs = 1.0f / (Sa * Sb);     // correctly-rounded reciprocal
        #pragma unroll
        for (int t = 0; t < 7; ++t) wa[t] *= rs;

        #pragma unroll
        for (int i = 0; i < 7; ++i)
            #pragma unroll
            for (int j = 0; j < 7; ++j)
                acc[i * 7 + j] = fmaf(wa[i], wb[j], acc[i * 7 + j]);
    }

    if (cur >= 0) {                            // final flush
        const int fa = cur >> 5, fb = cur & 31;
        #pragma unroll
        for (int i = 0; i < 7; ++i)
            #pragma unroll
            for (int j = 0; j < 7; ++j)
                atomicAdd(&sgrid[(fa + i) * NBIN + fb + j], (double)acc[i * 7 + j]);
    }
    __syncthreads();

    double* outp = g_bpart + ((size_t)b * NBLKD + blk) * CELLS;
    for (int c = tid; c < CELLS; c += 256) outp[c] = sgrid[c];
}

// ---- phase 5: per-batch reduce, marginals, MI (double) ----
__global__ __launch_bounds__(CELLS)
void mi_batch()
{
    __shared__ double pabS[CELLS];
    __shared__ double paS[NBIN], pbS[NBIN];
    __shared__ double red[CELLS];
    const int b = blockIdx.x, c = threadIdx.x;
    const double invN = 1.0 / (double)NVOX;

    double t = 0.0;
    #pragma unroll 4
    for (int blk = 0; blk < NBLKD; ++blk)
        t += g_bpart[((size_t)b * NBLKD + blk) * CELLS + c];
    pabS[c] = t;
    __syncthreads();

    if (c < NB) {
        double m = 0.0;
        for (int j = 0; j < NB; ++j) m += pabS[c * NBIN + j];
        paS[c] = m * invN;
    } else if (c >= 32 && c < 32 + NB) {
        const int j = c - 32;
        double m = 0.0;
        for (int i = 0; i < NB; ++i) m += pabS[i * NBIN + j];
        pbS[j] = m * invN;
    }
    __syncthreads();

    const int i = c / NBIN, j = c % NBIN;
    double term = 0.0;
    if (i < NB && j < NB) {
        const double pab  = pabS[c] * invN;
        const double papb = paS[i] * pbS[j];
        term = pab * log((pab + 1e-7) / (papb + 1e-7) + 1e-7);
    }
    red[c] = term;
    __syncthreads();

    if (c < 64) red[c] += red[c + 512];
    __syncthreads();
    for (int o = 256; o > 0; o >>= 1) {
        if (c < o) red[c] += red[c + o];
        __syncthreads();
    }
    if (c == 0) g_mi[b] = red[0];
}

__global__ void mi_final(float* __restrict__ out)
{
    double s = 0.0;
    for (int b = 0; b < BATCH; ++b) s += g_mi[b];
    out[0] = (float)(-s / (double)BATCH);
}

extern "C" void kernel_launch(void* const* d_in, const int* in_sizes, int n_in,
                              void* d_out, int out_size)
{
    (void)in_sizes; (void)n_in; (void)out_size;
    const float* pred   = (const float*)d_in[0];
    const float* target = (const float*)d_in[1];

    mi_hist <<<dim3(NBLKS, BATCH), 256>>>(pred, target);
    mi_scan <<<BATCH, 512>>>();
    mi_place<<<dim3(NBLKS, BATCH), 256>>>(pred, target);
    mi_accum<<<dim3(NBLKD, BATCH), 256>>>();
    mi_batch<<<BATCH, CELLS>>>();
    mi_final<<<1, 1>>>((float*)d_out);
}